// round 2
// baseline (speedup 1.0000x reference)
#include <cuda_runtime.h>
#include <stdint.h>
#include <math.h>

// ============================================================================
// SPEClassifier: full reimplementation of the JAX reference.
//
// Shapes: D=256, K=512, L=64, B=8, S=16, C=64.
// Heavy part: tl[half][b][l][s][j] needs 2*4*64*16*64*256 = 2^27 N(0,1)
// samples that must match jax.random.normal bit-for-bit (threefry2x32).
//
// JAX_PARTITIONABLE=1 -> jax_threefry_partitionable semantics (default in
// modern JAX): split is fold-like, random_bits elem i = x0^x1 of cipher(0,i).
// Set to 0 for legacy threefry mode (even/odd counter split, lane select).
// ============================================================================

#define JAX_PARTITIONABLE 1

// ---------------- device scratch (no allocation allowed) -------------------
__device__ int   g_order[512];            // [b(8)][l(64)] -> original row
__device__ float g_qm[8*64*256];          // by_class mean
__device__ float g_qv[8*64*256];          // by_class variance exp(h)
__device__ float g_pm[2*64*256];          // proto mean   per half
__device__ float g_pv[2*64*256];          // proto var    per half (eps_var+new_var)
__device__ float g_pC[2*64];              // -0.5*sum_d(log2pi + h_p)
__device__ float g_lm[2*4*64*64];         // logmls(query, proto)
__device__ float g_tl[2*4*64*16*64];      // MC logpdf sums

// ---------------- threefry2x32 (matches jax._src.prng) ---------------------
__host__ __device__ inline void tf2x32(uint32_t k0, uint32_t k1,
                                       uint32_t x0, uint32_t x1,
                                       uint32_t* o0, uint32_t* o1) {
  uint32_t k2 = k0 ^ k1 ^ 0x1BD11BDAu;
#ifdef __CUDA_ARCH__
#define ROTL(x,r) __funnelshift_l((x),(x),(r))
#else
#define ROTL(x,r) (((x)<<(r))|((x)>>(32-(r))))
#endif
#define RND(r) { x0 += x1; x1 = ROTL(x1, r); x1 ^= x0; }
  x0 += k0; x1 += k1;
  RND(13) RND(15) RND(26) RND(6)   x0 += k1; x1 += k2 + 1u;
  RND(17) RND(29) RND(16) RND(24)  x0 += k2; x1 += k0 + 2u;
  RND(13) RND(15) RND(26) RND(6)   x0 += k0; x1 += k1 + 3u;
  RND(17) RND(29) RND(16) RND(24)  x0 += k1; x1 += k2 + 4u;
  RND(13) RND(15) RND(26) RND(6)   x0 += k2; x1 += k0 + 5u;
#undef RND
#undef ROTL
  *o0 = x0; *o1 = x1;
}

// ---------------- erfinv, matching XLA's f32 expansion (Giles) -------------
__device__ __forceinline__ float erfinv_xla(float x) {
  float w = -log1pf(-x * x);
  float p;
  if (w < 5.0f) {
    w = w - 2.5f;
    p = 2.81022636e-08f;
    p = fmaf(p, w, 3.43273939e-07f);
    p = fmaf(p, w, -3.5233877e-06f);
    p = fmaf(p, w, -4.39150654e-06f);
    p = fmaf(p, w, 0.00021858087f);
    p = fmaf(p, w, -0.00125372503f);
    p = fmaf(p, w, -0.00417768164f);
    p = fmaf(p, w, 0.246640727f);
    p = fmaf(p, w, 1.50140941f);
  } else {
    w = sqrtf(w) - 3.0f;
    p = -0.000200214257f;
    p = fmaf(p, w, 0.000100950558f);
    p = fmaf(p, w, 0.00134934322f);
    p = fmaf(p, w, -0.00367342844f);
    p = fmaf(p, w, 0.00573950773f);
    p = fmaf(p, w, -0.0076224613f);
    p = fmaf(p, w, 0.00943887047f);
    p = fmaf(p, w, 1.00167406f);
    p = fmaf(p, w, 2.83297682f);
  }
  return p * x;
}

// ---------------- K1: stable counting "argsort" of labels ------------------
// Reads labels as int32 words (always safe: buffer >= 2048 bytes for both
// int32 and int64 layouts). Detects little-endian int64 (all odd words zero)
// and strides by 2 in that case. All g_order writes are bounds-guarded.
__global__ void order_kernel(const int* __restrict__ labels32) {
  __shared__ int slab[512];
  __shared__ int is64;
  int t = threadIdx.x;

  slab[t] = labels32[t];            // first 512 int32 words
  if (t == 0) is64 = 1;
  __syncthreads();
  // int64 layout => every odd word is the high half of a small value == 0
  if ((t & 1) && slab[t] != 0) atomicAnd(&is64, 0);
  __syncthreads();

  int c;
  if (is64) {
    // reload with stride 2 (buffer is 4096 bytes in this case)
    c = labels32[2 * t];
  } else {
    c = slab[t];
  }
  __syncthreads();
  slab[t] = c;
  __syncthreads();

  int occ = 0;
  for (int i = 0; i < t; i++) occ += (slab[i] == c) ? 1 : 0;
  if (c >= 0 && c < 64 && occ < 8)
    g_order[occ * 64 + c] = t;      // order[b][l] = original row index
}

// ---------------- K2: gather params into class-grouped layout --------------
__global__ void gather_kernel(const float* __restrict__ params) {
  int bx = blockIdx.x;
  int b = bx >> 6, l = bx & 63;
  int d = threadIdx.x;
  int row = g_order[b * 64 + l];
  int o = (b * 64 + l) * 256 + d;
  g_qm[o] = params[row * 512 + d];
  g_qv[o] = expf(params[row * 512 + 256 + d]);
}

// ---------------- K3: fuse support into prototypes per half ----------------
__global__ void proto_kernel(const float* __restrict__ heps) {
  int bx = blockIdx.x;
  int half = bx >> 6, l = bx & 63;
  int d = threadIdx.x;
  float eps_var = expf(*heps);
  int sb = half ? 0 : 4;  // half0 support = by_class[4:8], half1 = [0:4]
  float sinv = 0.f, smi = 0.f;
#pragma unroll
  for (int bi = 0; bi < 4; bi++) {
    int o = ((sb + bi) * 64 + l) * 256 + d;
    float v = eps_var + g_qv[o];
    float inv = 1.0f / v;
    sinv += inv;
    smi = fmaf(g_qm[o], inv, smi);
  }
  float nv = 1.0f / sinv;
  float nm = nv * smi;
  float vp = eps_var + nv;
  float hp = logf(vp);
  int po = (half * 64 + l) * 256 + d;
  g_pm[po] = nm;
  g_pv[po] = vp;
  __shared__ float red[256];
  red[d] = 1.83787707f + hp;   // log(2*pi) + h_p
  __syncthreads();
  for (int o = 128; o > 0; o >>= 1) {
    if (d < o) red[d] += red[d + o];
    __syncthreads();
  }
  if (d == 0) g_pC[half * 64 + l] = -0.5f * red[0];
}

// ---------------- K4: main Monte-Carlo kernel -------------------------------
// One block per (half, b, l, j); 128 threads. Phase 1 builds a[d], beta[d]
// and the logmls reduction; phase 2 generates 4096 eps and 16 dot products.
__global__ __launch_bounds__(128) void main_kernel(uint32_t s1k0, uint32_t s1k1,
                                                   uint32_t s2k0, uint32_t s2k1) {
  int bx = blockIdx.x;
  int j = bx & 63, l = (bx >> 6) & 63, b = (bx >> 12) & 3, half = bx >> 14;
  uint32_t k0 = half ? s2k0 : s1k0;
  uint32_t k1 = half ? s2k1 : s1k1;
  int qb = half * 4 + b;

  __shared__ float a_s[256];
  __shared__ float b_s[256];
  __shared__ float red4[4];

  int tid = threadIdx.x;
  int lane = tid & 31, warp = tid >> 5;

  const float* qm = g_qm + (qb * 64 + l) * 256;
  const float* qv = g_qv + (qb * 64 + l) * 256;
  const float* pm = g_pm + (half * 64 + j) * 256;
  const float* pv = g_pv + (half * 64 + j) * 256;

  float lmsum = 0.f;
#pragma unroll
  for (int dd = 0; dd < 2; dd++) {
    int d = tid + dd * 128;
    float m1 = qm[d], v1 = qv[d], m2 = pm[d], v2 = pv[d];
    float vs = v1 + v2;
    float rvs = 1.0f / vs;
    float dm = m1 - m2;
    a_s[d] = dm * sqrtf(v2) * rvs;       // a = dm*sqrt(v2)/(v1+v2)
    b_s[d] = sqrtf(v1 * rvs);            // beta = sqrt(v1/(v1+v2))
    lmsum += 1.8378770664f + logf(vs) + dm * dm * rvs;
  }
  // block reduce lmsum (128 threads)
  for (int o = 16; o > 0; o >>= 1) lmsum += __shfl_xor_sync(0xffffffffu, lmsum, o);
  if (lane == 0) red4[warp] = lmsum;
  __syncthreads();
  if (tid == 0) {
    float s = red4[0] + red4[1] + red4[2] + red4[3];
    g_lm[((half * 4 + b) * 64 + l) * 64 + j] = -0.5f * s;
  }

  // stage a/beta into registers: lane owns d = lane + 32u
  float ar[8], br[8];
#pragma unroll
  for (int u = 0; u < 8; u++) { ar[u] = a_s[lane + 32 * u]; br[u] = b_s[lane + 32 * u]; }

  float Cj = g_pC[half * 64 + j];
  const float LO = -0.99999994f;        // nextafterf(-1, 0)
  const float SPAN = 1.0f - LO;         // == 2.0f in f32

#pragma unroll
  for (int si = 0; si < 4; si++) {
    int s = si * 4 + warp;
    uint32_t ibase = ((((uint32_t)(b * 64 + l)) * 16u + (uint32_t)s) * 64u +
                      (uint32_t)j) * 256u;
    float acc = 0.f;
#pragma unroll
    for (int u = 0; u < 8; u++) {
      uint32_t i = ibase + (uint32_t)(lane + 32 * u);
      uint32_t o0, o1, bits;
#if JAX_PARTITIONABLE
      tf2x32(k0, k1, 0u, i, &o0, &o1);
      bits = o0 ^ o1;
#else
      if (b < 2) { tf2x32(k0, k1, i, i + 33554432u, &o0, &o1); bits = o0; }
      else       { tf2x32(k0, k1, i - 33554432u, i, &o0, &o1); bits = o1; }
#endif
      // uniform in [lo, 1): f in [0,1) from top-23 mantissa bits
      float f = __uint_as_float((bits >> 9) | 0x3f800000u) - 1.0f;
      float uu = fmaxf(LO, fmaf(f, SPAN, LO));
      float e = 1.41421356f * erfinv_xla(uu);   // sqrt(2)*erfinv = N(0,1)
      float t = fmaf(br[u], e, ar[u]);
      acc = fmaf(t, t, acc);
    }
    for (int o = 16; o > 0; o >>= 1) acc += __shfl_xor_sync(0xffffffffu, acc, o);
    if (lane == 0)
      g_tl[(((half * 4 + b) * 64 + l) * 16 + s) * 64 + j] = Cj - 0.5f * acc;
  }
}

// ---------------- K5: logsumexps + scatter to output ------------------------
__global__ void finalize_kernel(float* __restrict__ out) {
  int bx = blockIdx.x;
  int l = bx & 63, b = (bx >> 6) & 3, half = bx >> 8;
  int j = threadIdx.x;

  __shared__ float sh[16 * 64];
  __shared__ float nls[16];
  __shared__ float Msh;

  int base = (((half * 4 + b) * 64 + l) * 16) * 64;
  for (int s = 0; s < 16; s++) sh[s * 64 + j] = g_tl[base + s * 64 + j];
  __syncthreads();

  if (j < 16) {
    int s = j;
    float mx = -3.4e38f;
    for (int k = 0; k < 64; k++) mx = fmaxf(mx, sh[s * 64 + k]);
    float sum = 0.f;
    for (int k = 0; k < 64; k++) sum += expf(sh[s * 64 + k] - mx);
    nls[s] = -(mx + logf(sum));      // -lse[s]
  }
  __syncthreads();
  if (j == 0) {
    float mx = -3.4e38f;
    for (int s = 0; s < 16; s++) mx = fmaxf(mx, nls[s]);
    float sum = 0.f;
    for (int s = 0; s < 16; s++) sum += expf(nls[s] - mx);
    Msh = mx + logf(sum) - 2.7725887f;   // logsumexp_s(-lse) - log(16)
  }
  __syncthreads();

  int row = g_order[(half * 4 + b) * 64 + l];
  out[row * 64 + j] = g_lm[((half * 4 + b) * 64 + l) * 64 + j] + Msh;
}

// ---------------- launcher ---------------------------------------------------
extern "C" void kernel_launch(void* const* d_in, const int* in_sizes, int n_in,
                              void* d_out, int out_size) {
  // Route inputs by element count (robust to metadata ordering):
  //   parameters: 512*512 = 262144 or 512*512? params is (512, 512) floats
  //   = 262144 elements; hidden_epsilon: 1; labels: 512.
  const float* params = nullptr;
  const float* heps   = nullptr;
  const int*   labels = nullptr;
  for (int i = 0; i < n_in; i++) {
    if (in_sizes[i] == 1) heps = (const float*)d_in[i];
    else if (in_sizes[i] == 512) labels = (const int*)d_in[i];
    else params = (const float*)d_in[i];
  }
  // Fallback to positional if anything missing
  if (!params) params = (const float*)d_in[0];
  if (!heps)   heps   = (const float*)d_in[1];
  if (!labels) labels = (const int*)d_in[2];

  float* out = (float*)d_out;
  (void)out_size;

  // key = jax.random.key(42) -> (0, 42); s1, s2 = split(key)
  uint32_t s1k0, s1k1, s2k0, s2k1;
#if JAX_PARTITIONABLE
  tf2x32(0u, 42u, 0u, 0u, &s1k0, &s1k1);   // fold-like split: cipher(key,(0,i))
  tf2x32(0u, 42u, 0u, 1u, &s2k0, &s2k1);
#else
  uint32_t a0, a1, c0, c1;
  tf2x32(0u, 42u, 0u, 2u, &a0, &a1);       // legacy split: counts [0,1,2,3]
  tf2x32(0u, 42u, 1u, 3u, &c0, &c1);
  s1k0 = a0; s1k1 = c0; s2k0 = a1; s2k1 = c1;
#endif

  order_kernel<<<1, 512>>>(labels);
  gather_kernel<<<512, 256>>>(params);
  proto_kernel<<<128, 256>>>(heps);
  main_kernel<<<32768, 128>>>(s1k0, s1k1, s2k0, s2k1);
  finalize_kernel<<<512, 64>>>(out);
}

// round 3
// speedup vs baseline: 1.2197x; 1.2197x over previous
#include <cuda_runtime.h>
#include <stdint.h>
#include <math.h>

// ============================================================================
// SPEClassifier on GB300. Shapes: D=256, K=512, L=64, B=8, S=16, C=64.
// 2^27 threefry2x32 ciphers (jax partitionable mode) dominate; kernel is
// integer-ALU bound. R3: force threefry adds onto the FMA pipe (IMAD via
// mad.lo.u32 with runtime-opaque multiplier), replace log1pf with
// fmaf(-u,u,1)+MUFU.LG2, fold sqrt(2) into erfinv coefficients, drop
// provably-redundant fmax.
// ============================================================================

// ---------------- device scratch (no allocation allowed) -------------------
__device__ int   g_order[512];            // [b(8)][l(64)] -> original row
__device__ float g_qm[8*64*256];          // by_class mean
__device__ float g_qv[8*64*256];          // by_class variance exp(h)
__device__ float g_pm[2*64*256];          // proto mean   per half
__device__ float g_pv[2*64*256];          // proto var    per half
__device__ float g_pC[2*64];              // -0.5*sum_d(log2pi + h_p)
__device__ float g_lm[2*4*64*64];         // logmls(query, proto)
__device__ float g_tl[2*4*64*16*64];      // MC logpdf sums

// ---------------- host threefry (key derivation) ---------------------------
static inline void tf2x32_host(uint32_t k0, uint32_t k1, uint32_t x0, uint32_t x1,
                               uint32_t* o0, uint32_t* o1) {
  uint32_t k2 = k0 ^ k1 ^ 0x1BD11BDAu;
#define ROTL(x,r) (((x)<<(r))|((x)>>(32-(r))))
#define RND(r) { x0 += x1; x1 = ROTL(x1, r); x1 ^= x0; }
  x0 += k0; x1 += k1;
  RND(13) RND(15) RND(26) RND(6)   x0 += k1; x1 += k2 + 1u;
  RND(17) RND(29) RND(16) RND(24)  x0 += k2; x1 += k0 + 2u;
  RND(13) RND(15) RND(26) RND(6)   x0 += k0; x1 += k1 + 3u;
  RND(17) RND(29) RND(16) RND(24)  x0 += k1; x1 += k2 + 4u;
  RND(13) RND(15) RND(26) RND(6)   x0 += k2; x1 += k0 + 5u;
#undef RND
#undef ROTL
  *o0 = x0; *o1 = x1;
}

// ---------------- device threefry with FMA-pipe adds -----------------------
// r = a*one + b, with `one` a kernel argument (runtime value 1) so ptxas
// must emit IMAD (fma pipe), relieving the saturated ALU pipe (SHF/LOP3).
__device__ __forceinline__ uint32_t madd1(uint32_t a, uint32_t b, uint32_t one) {
  uint32_t r;
  asm("mad.lo.u32 %0, %1, %2, %3;" : "=r"(r) : "r"(a), "r"(one), "r"(b));
  return r;
}

// Partitionable-mode bits for counter (0, i): returns x0 ^ x1.
__device__ __forceinline__ uint32_t tf_bits(uint32_t k0, uint32_t k1, uint32_t k2,
                                            uint32_t i, uint32_t one) {
  uint32_t x0 = k0;                  // 0 + k0
  uint32_t x1 = madd1(i, k1, one);   // i + k1
#define RND(r) { x0 = madd1(x0, x1, one); x1 = __funnelshift_l(x1, x1, r); x1 ^= x0; }
  RND(13) RND(15) RND(26) RND(6)
  x0 = madd1(x0, k1, one); x1 = madd1(x1, k2 + 1u, one);
  RND(17) RND(29) RND(16) RND(24)
  x0 = madd1(x0, k2, one); x1 = madd1(x1, k0 + 2u, one);
  RND(13) RND(15) RND(26) RND(6)
  x0 = madd1(x0, k0, one); x1 = madd1(x1, k1 + 3u, one);
  RND(17) RND(29) RND(16) RND(24)
  x0 = madd1(x0, k1, one); x1 = madd1(x1, k2 + 4u, one);
  RND(13) RND(15) RND(26) RND(6)
  x0 = madd1(x0, k2, one); x1 = madd1(x1, k0 + 5u, one);
#undef RND
  return x0 ^ x1;
}

// sqrt(2)*erfinv(u), coefficients pre-scaled by sqrt(2) at compile time.
// w = -log(1-u^2) computed as single-rounded fmaf + MUFU.LG2 (cheap & accurate).
__device__ __forceinline__ float sqrt2_erfinv(float u) {
  const float S = 1.41421356237f;
  float z = fmaf(-u, u, 1.0f);         // exact-ish 1-u^2 (single rounding)
  float L = __log2f(z);                // MUFU.LG2
  float p;
  if (L > -7.2134752044f) {            // w = -L*ln2 < 5
    float v = fmaf(L, -0.69314718056f, -2.5f);   // w - 2.5
    p = 2.81022636e-08f * S;
    p = fmaf(p, v, 3.43273939e-07f * S);
    p = fmaf(p, v, -3.5233877e-06f * S);
    p = fmaf(p, v, -4.39150654e-06f * S);
    p = fmaf(p, v, 0.00021858087f * S);
    p = fmaf(p, v, -0.00125372503f * S);
    p = fmaf(p, v, -0.00417768164f * S);
    p = fmaf(p, v, 0.246640727f * S);
    p = fmaf(p, v, 1.50140941f * S);
  } else {
    float w = L * -0.69314718056f;
    float v = sqrtf(w) - 3.0f;
    p = -0.000200214257f * S;
    p = fmaf(p, v, 0.000100950558f * S);
    p = fmaf(p, v, 0.00134934322f * S);
    p = fmaf(p, v, -0.00367342844f * S);
    p = fmaf(p, v, 0.00573950773f * S);
    p = fmaf(p, v, -0.0076224613f * S);
    p = fmaf(p, v, 0.00943887047f * S);
    p = fmaf(p, v, 1.00167406f * S);
    p = fmaf(p, v, 2.83297682f * S);
  }
  return p * u;
}

// ---------------- K1: stable counting "argsort" of labels ------------------
__global__ void order_kernel(const int* __restrict__ labels32) {
  __shared__ int slab[512];
  __shared__ int is64;
  int t = threadIdx.x;
  slab[t] = labels32[t];
  if (t == 0) is64 = 1;
  __syncthreads();
  if ((t & 1) && slab[t] != 0) atomicAnd(&is64, 0);
  __syncthreads();
  int c = is64 ? labels32[2 * t] : slab[t];
  __syncthreads();
  slab[t] = c;
  __syncthreads();
  int occ = 0;
  for (int i = 0; i < t; i++) occ += (slab[i] == c) ? 1 : 0;
  if (c >= 0 && c < 64 && occ < 8)
    g_order[occ * 64 + c] = t;
}

// ---------------- K2: gather params into class-grouped layout --------------
__global__ void gather_kernel(const float* __restrict__ params) {
  int bx = blockIdx.x;
  int b = bx >> 6, l = bx & 63;
  int d = threadIdx.x;
  int row = g_order[b * 64 + l];
  int o = (b * 64 + l) * 256 + d;
  g_qm[o] = params[row * 512 + d];
  g_qv[o] = expf(params[row * 512 + 256 + d]);
}

// ---------------- K3: fuse support into prototypes per half ----------------
__global__ void proto_kernel(const float* __restrict__ heps) {
  int bx = blockIdx.x;
  int half = bx >> 6, l = bx & 63;
  int d = threadIdx.x;
  float eps_var = expf(*heps);
  int sb = half ? 0 : 4;
  float sinv = 0.f, smi = 0.f;
#pragma unroll
  for (int bi = 0; bi < 4; bi++) {
    int o = ((sb + bi) * 64 + l) * 256 + d;
    float v = eps_var + g_qv[o];
    float inv = 1.0f / v;
    sinv += inv;
    smi = fmaf(g_qm[o], inv, smi);
  }
  float nv = 1.0f / sinv;
  float nm = nv * smi;
  float vp = eps_var + nv;
  float hp = logf(vp);
  int po = (half * 64 + l) * 256 + d;
  g_pm[po] = nm;
  g_pv[po] = vp;
  __shared__ float red[256];
  red[d] = 1.83787707f + hp;
  __syncthreads();
  for (int o = 128; o > 0; o >>= 1) {
    if (d < o) red[d] += red[d + o];
    __syncthreads();
  }
  if (d == 0) g_pC[half * 64 + l] = -0.5f * red[0];
}

// ---------------- K4: main Monte-Carlo kernel -------------------------------
__global__ __launch_bounds__(128) void main_kernel(uint32_t s1k0, uint32_t s1k1,
                                                   uint32_t s2k0, uint32_t s2k1,
                                                   uint32_t one) {
  int bx = blockIdx.x;
  int j = bx & 63, l = (bx >> 6) & 63, b = (bx >> 12) & 3, half = bx >> 14;
  uint32_t k0 = half ? s2k0 : s1k0;
  uint32_t k1 = half ? s2k1 : s1k1;
  uint32_t k2 = k0 ^ k1 ^ 0x1BD11BDAu;
  int qb = half * 4 + b;

  __shared__ float a_s[256];
  __shared__ float b_s[256];
  __shared__ float red4[4];

  int tid = threadIdx.x;
  int lane = tid & 31, warp = tid >> 5;

  const float* qm = g_qm + (qb * 64 + l) * 256;
  const float* qv = g_qv + (qb * 64 + l) * 256;
  const float* pm = g_pm + (half * 64 + j) * 256;
  const float* pv = g_pv + (half * 64 + j) * 256;

  float lmsum = 0.f;
#pragma unroll
  for (int dd = 0; dd < 2; dd++) {
    int d = tid + dd * 128;
    float m1 = qm[d], v1 = qv[d], m2 = pm[d], v2 = pv[d];
    float vs = v1 + v2;
    float rvs = 1.0f / vs;
    float dm = m1 - m2;
    a_s[d] = dm * sqrtf(v2) * rvs;       // a = dm*sqrt(v2)/(v1+v2)
    b_s[d] = sqrtf(v1 * rvs);            // beta = sqrt(v1/(v1+v2))
    lmsum += 1.8378770664f + logf(vs) + dm * dm * rvs;
  }
  for (int o = 16; o > 0; o >>= 1) lmsum += __shfl_xor_sync(0xffffffffu, lmsum, o);
  if (lane == 0) red4[warp] = lmsum;
  __syncthreads();
  if (tid == 0) {
    float s = red4[0] + red4[1] + red4[2] + red4[3];
    g_lm[((half * 4 + b) * 64 + l) * 64 + j] = -0.5f * s;
  }

  float ar[8], br[8];
#pragma unroll
  for (int u = 0; u < 8; u++) { ar[u] = a_s[lane + 32 * u]; br[u] = b_s[lane + 32 * u]; }

  float Cj = g_pC[half * 64 + j];
  const float LO = -0.99999994f;        // nextafterf(-1, 0)

#pragma unroll
  for (int si = 0; si < 4; si++) {
    int s = si * 4 + warp;
    uint32_t ibase = ((((uint32_t)(b * 64 + l)) * 16u + (uint32_t)s) * 64u +
                      (uint32_t)j) * 256u + (uint32_t)lane;
    float acc = 0.f;
#pragma unroll
    for (int u = 0; u < 8; u++) {
      uint32_t bits = tf_bits(k0, k1, k2, ibase + 32u * (uint32_t)u, one);
      // uniform in [LO, 1): top-23 mantissa bits; fmax(LO,.) provably no-op
      float f = __uint_as_float((bits >> 9) | 0x3f800000u) - 1.0f;
      float uu = fmaf(f, 2.0f, LO);
      float e = sqrt2_erfinv(uu);               // N(0,1) sample
      float t = fmaf(br[u], e, ar[u]);
      acc = fmaf(t, t, acc);
    }
    for (int o = 16; o > 0; o >>= 1) acc += __shfl_xor_sync(0xffffffffu, acc, o);
    if (lane == 0)
      g_tl[(((half * 4 + b) * 64 + l) * 16 + s) * 64 + j] = Cj - 0.5f * acc;
  }
}

// ---------------- K5: logsumexps + scatter to output ------------------------
__global__ void finalize_kernel(float* __restrict__ out) {
  int bx = blockIdx.x;
  int l = bx & 63, b = (bx >> 6) & 3, half = bx >> 8;
  int j = threadIdx.x;

  __shared__ float sh[16 * 64];
  __shared__ float nls[16];
  __shared__ float Msh;

  int base = (((half * 4 + b) * 64 + l) * 16) * 64;
  for (int s = 0; s < 16; s++) sh[s * 64 + j] = g_tl[base + s * 64 + j];
  __syncthreads();

  if (j < 16) {
    int s = j;
    float mx = -3.4e38f;
    for (int k = 0; k < 64; k++) mx = fmaxf(mx, sh[s * 64 + k]);
    float sum = 0.f;
    for (int k = 0; k < 64; k++) sum += expf(sh[s * 64 + k] - mx);
    nls[s] = -(mx + logf(sum));
  }
  __syncthreads();
  if (j == 0) {
    float mx = -3.4e38f;
    for (int s = 0; s < 16; s++) mx = fmaxf(mx, nls[s]);
    float sum = 0.f;
    for (int s = 0; s < 16; s++) sum += expf(nls[s] - mx);
    Msh = mx + logf(sum) - 2.7725887f;
  }
  __syncthreads();

  int row = g_order[(half * 4 + b) * 64 + l];
  out[row * 64 + j] = g_lm[((half * 4 + b) * 64 + l) * 64 + j] + Msh;
}

// ---------------- launcher ---------------------------------------------------
extern "C" void kernel_launch(void* const* d_in, const int* in_sizes, int n_in,
                              void* d_out, int out_size) {
  const float* params = nullptr;
  const float* heps   = nullptr;
  const int*   labels = nullptr;
  for (int i = 0; i < n_in; i++) {
    if (in_sizes[i] == 1) heps = (const float*)d_in[i];
    else if (in_sizes[i] == 512) labels = (const int*)d_in[i];
    else params = (const float*)d_in[i];
  }
  if (!params) params = (const float*)d_in[0];
  if (!heps)   heps   = (const float*)d_in[1];
  if (!labels) labels = (const int*)d_in[2];

  float* out = (float*)d_out;
  (void)out_size;

  // key = jax.random.key(42); s1, s2 = split(key)  (partitionable fold)
  uint32_t s1k0, s1k1, s2k0, s2k1;
  tf2x32_host(0u, 42u, 0u, 0u, &s1k0, &s1k1);
  tf2x32_host(0u, 42u, 0u, 1u, &s2k0, &s2k1);

  order_kernel<<<1, 512>>>(labels);
  gather_kernel<<<512, 256>>>(params);
  proto_kernel<<<128, 256>>>(heps);
  main_kernel<<<32768, 128>>>(s1k0, s1k1, s2k0, s2k1, 1u);
  finalize_kernel<<<512, 64>>>(out);
}

// round 4
// speedup vs baseline: 1.2590x; 1.0322x over previous
#include <cuda_runtime.h>
#include <stdint.h>
#include <math.h>

// ============================================================================
// SPEClassifier on GB300. Shapes: D=256, K=512, L=64, B=8, S=16, C=64.
// 2^27 threefry2x32 ciphers (jax partitionable mode); issue/ALU bound.
// R4: u-outer/si-inner loop (regs 43->~32, occupancy up), IMAD.HI mantissa
// trick, alu/fma pipe rebalance (3 adds demoted to IADD3).
// ============================================================================

// ---------------- device scratch (no allocation allowed) -------------------
__device__ int   g_order[512];            // [b(8)][l(64)] -> original row
__device__ float g_qm[8*64*256];          // by_class mean
__device__ float g_qv[8*64*256];          // by_class variance exp(h)
__device__ float g_pm[2*64*256];          // proto mean   per half
__device__ float g_pv[2*64*256];          // proto var    per half
__device__ float g_pC[2*64];              // -0.5*sum_d(log2pi + h_p)
__device__ float g_lm[2*4*64*64];         // logmls(query, proto)
__device__ float g_tl[2*4*64*16*64];      // MC logpdf sums

// ---------------- host threefry (key derivation) ---------------------------
static inline void tf2x32_host(uint32_t k0, uint32_t k1, uint32_t x0, uint32_t x1,
                               uint32_t* o0, uint32_t* o1) {
  uint32_t k2 = k0 ^ k1 ^ 0x1BD11BDAu;
#define ROTL(x,r) (((x)<<(r))|((x)>>(32-(r))))
#define RND(r) { x0 += x1; x1 = ROTL(x1, r); x1 ^= x0; }
  x0 += k0; x1 += k1;
  RND(13) RND(15) RND(26) RND(6)   x0 += k1; x1 += k2 + 1u;
  RND(17) RND(29) RND(16) RND(24)  x0 += k2; x1 += k0 + 2u;
  RND(13) RND(15) RND(26) RND(6)   x0 += k0; x1 += k1 + 3u;
  RND(17) RND(29) RND(16) RND(24)  x0 += k1; x1 += k2 + 4u;
  RND(13) RND(15) RND(26) RND(6)   x0 += k2; x1 += k0 + 5u;
#undef RND
#undef ROTL
  *o0 = x0; *o1 = x1;
}

// r = a*one + b with runtime-opaque one==1 -> IMAD on the FMA pipe.
__device__ __forceinline__ uint32_t madd1(uint32_t a, uint32_t b, uint32_t one) {
  uint32_t r;
  asm("mad.lo.u32 %0, %1, %2, %3;" : "=r"(r) : "r"(a), "r"(one), "r"(b));
  return r;
}

// Partitionable-mode bits for counter (0, i): returns x0 ^ x1.
// 3 adds intentionally left as plain + (IADD3/alu) for pipe balance.
__device__ __forceinline__ uint32_t tf_bits(uint32_t k0, uint32_t k1, uint32_t k2,
                                            uint32_t i, uint32_t one) {
  uint32_t x0 = k0;
  uint32_t x1 = i + k1;              // alu
#define RND(r) { x0 = madd1(x0, x1, one); x1 = __funnelshift_l(x1, x1, r); x1 ^= x0; }
  RND(13) RND(15) RND(26) RND(6)
  x0 = madd1(x0, k1, one); x1 = madd1(x1, k2 + 1u, one);
  RND(17) RND(29) RND(16) RND(24)
  x0 = madd1(x0, k2, one); x1 = madd1(x1, k0 + 2u, one);
  RND(13) RND(15) RND(26) RND(6)
  x0 = madd1(x0, k0, one); x1 = madd1(x1, k1 + 3u, one);
  RND(17) RND(29) RND(16) RND(24)
  x0 = madd1(x0, k1, one); x1 = madd1(x1, k2 + 4u, one);
  RND(13) RND(15) RND(26) RND(6)
  x0 = x0 + k2;                      // alu
  x1 = x1 + (k0 + 5u);               // alu
#undef RND
  return x0 ^ x1;
}

// N(0,1) sample from 32 random bits, bit-identical to jax.random.normal path:
// u = uniform(lo,1), sqrt(2)*erfinv(u) with sqrt(2) folded into coefficients.
__device__ __forceinline__ float bits_to_normal(uint32_t bits) {
  const float S = 1.41421356237f;
  const float LO = -0.99999994f;     // nextafterf(-1, 0)
  // m = float with exponent 0, mantissa = bits>>9  (IMAD.HI, fma pipe)
  uint32_t mi;
  asm("mad.hi.u32 %0, %1, %2, %3;" : "=r"(mi)
      : "r"(bits), "n"(0x800000), "n"(0x3f800000));
  float f = __uint_as_float(mi) - 1.0f;      // exact, in [0,1)
  float u = fmaf(f, 2.0f, LO);               // single rounding (matches jax)
  float z = fmaf(-u, u, 1.0f);               // 1-u^2, single rounding
  float L = __log2f(z);                      // MUFU.LG2
  float p;
  if (L > -7.2134752044f) {                  // w = -L*ln2 < 5
    float v = fmaf(L, -0.69314718056f, -2.5f);
    p = 2.81022636e-08f * S;
    p = fmaf(p, v, 3.43273939e-07f * S);
    p = fmaf(p, v, -3.5233877e-06f * S);
    p = fmaf(p, v, -4.39150654e-06f * S);
    p = fmaf(p, v, 0.00021858087f * S);
    p = fmaf(p, v, -0.00125372503f * S);
    p = fmaf(p, v, -0.00417768164f * S);
    p = fmaf(p, v, 0.246640727f * S);
    p = fmaf(p, v, 1.50140941f * S);
  } else {
    float w = L * -0.69314718056f;
    float v = sqrtf(w) - 3.0f;
    p = -0.000200214257f * S;
    p = fmaf(p, v, 0.000100950558f * S);
    p = fmaf(p, v, 0.00134934322f * S);
    p = fmaf(p, v, -0.00367342844f * S);
    p = fmaf(p, v, 0.00573950773f * S);
    p = fmaf(p, v, -0.0076224613f * S);
    p = fmaf(p, v, 0.00943887047f * S);
    p = fmaf(p, v, 1.00167406f * S);
    p = fmaf(p, v, 2.83297682f * S);
  }
  return p * u;
}

// ---------------- K1: stable counting "argsort" of labels ------------------
__global__ void order_kernel(const int* __restrict__ labels32) {
  __shared__ int slab[512];
  __shared__ int is64;
  int t = threadIdx.x;
  slab[t] = labels32[t];
  if (t == 0) is64 = 1;
  __syncthreads();
  if ((t & 1) && slab[t] != 0) atomicAnd(&is64, 0);
  __syncthreads();
  int c = is64 ? labels32[2 * t] : slab[t];
  __syncthreads();
  slab[t] = c;
  __syncthreads();
  int occ = 0;
  for (int i = 0; i < t; i++) occ += (slab[i] == c) ? 1 : 0;
  if (c >= 0 && c < 64 && occ < 8)
    g_order[occ * 64 + c] = t;
}

// ---------------- K2: gather params into class-grouped layout --------------
__global__ void gather_kernel(const float* __restrict__ params) {
  int bx = blockIdx.x;
  int b = bx >> 6, l = bx & 63;
  int d = threadIdx.x;
  int row = g_order[b * 64 + l];
  int o = (b * 64 + l) * 256 + d;
  g_qm[o] = params[row * 512 + d];
  g_qv[o] = expf(params[row * 512 + 256 + d]);
}

// ---------------- K3: fuse support into prototypes per half ----------------
__global__ void proto_kernel(const float* __restrict__ heps) {
  int bx = blockIdx.x;
  int half = bx >> 6, l = bx & 63;
  int d = threadIdx.x;
  float eps_var = expf(*heps);
  int sb = half ? 0 : 4;
  float sinv = 0.f, smi = 0.f;
#pragma unroll
  for (int bi = 0; bi < 4; bi++) {
    int o = ((sb + bi) * 64 + l) * 256 + d;
    float v = eps_var + g_qv[o];
    float inv = 1.0f / v;
    sinv += inv;
    smi = fmaf(g_qm[o], inv, smi);
  }
  float nv = 1.0f / sinv;
  float nm = nv * smi;
  float vp = eps_var + nv;
  float hp = logf(vp);
  int po = (half * 64 + l) * 256 + d;
  g_pm[po] = nm;
  g_pv[po] = vp;
  __shared__ float red[256];
  red[d] = 1.83787707f + hp;
  __syncthreads();
  for (int o = 128; o > 0; o >>= 1) {
    if (d < o) red[d] += red[d + o];
    __syncthreads();
  }
  if (d == 0) g_pC[half * 64 + l] = -0.5f * red[0];
}

// ---------------- K4: main Monte-Carlo kernel -------------------------------
// Block = (half, b, l, j), 128 threads. Warp w handles s in {w, w+4, w+8, w+12}
// via 4 concurrent accumulators; u (d-chunk) is the outer 8x unrolled loop.
__global__ __launch_bounds__(128, 14) void main_kernel(uint32_t s1k0, uint32_t s1k1,
                                                       uint32_t s2k0, uint32_t s2k1,
                                                       uint32_t one) {
  int bx = blockIdx.x;
  int j = bx & 63, l = (bx >> 6) & 63, b = (bx >> 12) & 3, half = bx >> 14;
  uint32_t k0 = half ? s2k0 : s1k0;
  uint32_t k1 = half ? s2k1 : s1k1;
  uint32_t k2 = k0 ^ k1 ^ 0x1BD11BDAu;
  int qb = half * 4 + b;

  __shared__ float a_s[256];
  __shared__ float b_s[256];
  __shared__ float red4[4];

  int tid = threadIdx.x;
  int lane = tid & 31, warp = tid >> 5;

  const float* qm = g_qm + (qb * 64 + l) * 256;
  const float* qv = g_qv + (qb * 64 + l) * 256;
  const float* pm = g_pm + (half * 64 + j) * 256;
  const float* pv = g_pv + (half * 64 + j) * 256;

  float lmsum = 0.f;
#pragma unroll
  for (int dd = 0; dd < 2; dd++) {
    int d = tid + dd * 128;
    float m1 = qm[d], v1 = qv[d], m2 = pm[d], v2 = pv[d];
    float vs = v1 + v2;
    float rvs = 1.0f / vs;
    float dm = m1 - m2;
    a_s[d] = dm * sqrtf(v2) * rvs;       // a = dm*sqrt(v2)/(v1+v2)
    b_s[d] = sqrtf(v1 * rvs);            // beta = sqrt(v1/(v1+v2))
    lmsum += 1.8378770664f + logf(vs) + dm * dm * rvs;
  }
  for (int o = 16; o > 0; o >>= 1) lmsum += __shfl_xor_sync(0xffffffffu, lmsum, o);
  if (lane == 0) red4[warp] = lmsum;
  __syncthreads();
  if (tid == 0) {
    float s = red4[0] + red4[1] + red4[2] + red4[3];
    g_lm[((half * 4 + b) * 64 + l) * 64 + j] = -0.5f * s;
  }

  float Cj = g_pC[half * 64 + j];

  // counter for (s=warp, u=0, d=lane); deltas: s+=4 -> +65536, u+=1 -> +32
  uint32_t i00 = ((((uint32_t)(b * 64 + l)) * 16u + (uint32_t)warp) * 64u +
                  (uint32_t)j) * 256u + (uint32_t)lane;

  float acc0 = 0.f, acc1 = 0.f, acc2 = 0.f, acc3 = 0.f;

#pragma unroll
  for (int u = 0; u < 8; u++) {
    float a = a_s[lane + 32 * u];
    float bb = b_s[lane + 32 * u];
    uint32_t iu = i00 + 32u * (uint32_t)u;

    float e0 = bits_to_normal(tf_bits(k0, k1, k2, iu,           one));
    float e1 = bits_to_normal(tf_bits(k0, k1, k2, iu + 65536u,  one));
    float e2 = bits_to_normal(tf_bits(k0, k1, k2, iu + 131072u, one));
    float e3 = bits_to_normal(tf_bits(k0, k1, k2, iu + 196608u, one));

    float t0 = fmaf(bb, e0, a); acc0 = fmaf(t0, t0, acc0);
    float t1 = fmaf(bb, e1, a); acc1 = fmaf(t1, t1, acc1);
    float t2 = fmaf(bb, e2, a); acc2 = fmaf(t2, t2, acc2);
    float t3 = fmaf(bb, e3, a); acc3 = fmaf(t3, t3, acc3);
  }

#pragma unroll
  for (int o = 16; o > 0; o >>= 1) {
    acc0 += __shfl_xor_sync(0xffffffffu, acc0, o);
    acc1 += __shfl_xor_sync(0xffffffffu, acc1, o);
    acc2 += __shfl_xor_sync(0xffffffffu, acc2, o);
    acc3 += __shfl_xor_sync(0xffffffffu, acc3, o);
  }
  if (lane == 0) {
    int base = (((half * 4 + b) * 64 + l) * 16 + warp) * 64 + j;
    g_tl[base]            = Cj - 0.5f * acc0;   // s = warp
    g_tl[base + 4 * 64]   = Cj - 0.5f * acc1;   // s = warp + 4
    g_tl[base + 8 * 64]   = Cj - 0.5f * acc2;   // s = warp + 8
    g_tl[base + 12 * 64]  = Cj - 0.5f * acc3;   // s = warp + 12
  }
}

// ---------------- K5: logsumexps + scatter to output ------------------------
__global__ void finalize_kernel(float* __restrict__ out) {
  int bx = blockIdx.x;
  int l = bx & 63, b = (bx >> 6) & 3, half = bx >> 8;
  int j = threadIdx.x;

  __shared__ float sh[16 * 64];
  __shared__ float nls[16];
  __shared__ float Msh;

  int base = (((half * 4 + b) * 64 + l) * 16) * 64;
  for (int s = 0; s < 16; s++) sh[s * 64 + j] = g_tl[base + s * 64 + j];
  __syncthreads();

  if (j < 16) {
    int s = j;
    float mx = -3.4e38f;
    for (int k = 0; k < 64; k++) mx = fmaxf(mx, sh[s * 64 + k]);
    float sum = 0.f;
    for (int k = 0; k < 64; k++) sum += expf(sh[s * 64 + k] - mx);
    nls[s] = -(mx + logf(sum));
  }
  __syncthreads();
  if (j == 0) {
    float mx = -3.4e38f;
    for (int s = 0; s < 16; s++) mx = fmaxf(mx, nls[s]);
    float sum = 0.f;
    for (int s = 0; s < 16; s++) sum += expf(nls[s] - mx);
    Msh = mx + logf(sum) - 2.7725887f;
  }
  __syncthreads();

  int row = g_order[(half * 4 + b) * 64 + l];
  out[row * 64 + j] = g_lm[((half * 4 + b) * 64 + l) * 64 + j] + Msh;
}

// ---------------- launcher ---------------------------------------------------
extern "C" void kernel_launch(void* const* d_in, const int* in_sizes, int n_in,
                              void* d_out, int out_size) {
  const float* params = nullptr;
  const float* heps   = nullptr;
  const int*   labels = nullptr;
  for (int i = 0; i < n_in; i++) {
    if (in_sizes[i] == 1) heps = (const float*)d_in[i];
    else if (in_sizes[i] == 512) labels = (const int*)d_in[i];
    else params = (const float*)d_in[i];
  }
  if (!params) params = (const float*)d_in[0];
  if (!heps)   heps   = (const float*)d_in[1];
  if (!labels) labels = (const int*)d_in[2];

  float* out = (float*)d_out;
  (void)out_size;

  // key = jax.random.key(42); s1, s2 = split(key)  (partitionable fold)
  uint32_t s1k0, s1k1, s2k0, s2k1;
  tf2x32_host(0u, 42u, 0u, 0u, &s1k0, &s1k1);
  tf2x32_host(0u, 42u, 0u, 1u, &s2k0, &s2k1);

  order_kernel<<<1, 512>>>(labels);
  gather_kernel<<<512, 256>>>(params);
  proto_kernel<<<128, 256>>>(heps);
  main_kernel<<<32768, 128>>>(s1k0, s1k1, s2k0, s2k1, 1u);
  finalize_kernel<<<512, 64>>>(out);
}